// round 10
// baseline (speedup 1.0000x reference)
#include <cuda_runtime.h>
#include <cuda_bf16.h>
#include <math.h>
#include <cstdint>
#include <limits.h>

// ---------------- problem constants ----------------
#define B_    4
#define N_    10000
#define E_    160000
#define M_    (B_*N_)        // 40000 rows (m = b*N + n)
#define NC1   576            // GEMM1 cols: 3*128 (ru views) + 3*64 (c input views)
#define NC2   192            // GEMM2 cols: 3*64 (c hidden views)
#define MTILE ((M_ + 127)/128)   // 313 row tiles

// ---------------- scratch (static device globals; no runtime alloc) ----------------
__device__ __nv_bfloat16 g_Xh[M_*128];   // hi(concat(inputs,hx))
__device__ __nv_bfloat16 g_Xl[M_*128];   // lo part
__device__ __nv_bfloat16 g_gh[M_*64];    // hi(r*hx)
__device__ __nv_bfloat16 g_gl[M_*64];
__device__ __nv_bfloat16 g_W1h[NC1*128]; // GEMM1 weights, [c][k]
__device__ __nv_bfloat16 g_W1l[NC1*128];
__device__ __nv_bfloat16 g_W2h[NC2*64];
__device__ __nv_bfloat16 g_W2l[NC2*64];
__device__ float g_Pru[3][M_*128];       // ru fp32 views
__device__ float g_Qc [3][M_*64];        // c  fp32 views
__device__ float g_U  [M_*64];           // u gate
__device__ int   g_deg[N_];
__device__ int   g_rowptr[N_+1];
__device__ int   g_cursor[N_];
__device__ int   g_tmpeid[E_];
__device__ int2  g_csr[E_];              // packed (src, ker bits)

// compile-time scratch-buffer selector: 0..2 -> g_Pru[v], 3..5 -> g_Qc[v-3]
template<int ID>
__device__ __forceinline__ float* sel_buf() {
    if constexpr (ID < 3) return g_Pru[ID];
    else                  return g_Qc[ID-3];
}

// ---------------- PTX helpers (baseline ISA only) ----------------
__device__ __forceinline__ uint32_t smem_u32(const void* p) {
    uint32_t a;
    asm("{ .reg .u64 t; cvta.to.shared.u64 t, %1; cvt.u32.u64 %0, t; }" : "=r"(a) : "l"(p));
    return a;
}
__device__ __forceinline__ void cp16(uint32_t dst, const void* src, bool full) {
    int sz = full ? 16 : 0;
    asm volatile("cp.async.cg.shared.global [%0], [%1], 16, %2;"
                 :: "r"(dst), "l"(src), "r"(sz) : "memory");
}
#define CP_COMMIT()  asm volatile("cp.async.commit_group;" ::: "memory")
#define CP_WAIT(n)   asm volatile("cp.async.wait_group %0;" :: "n"(n) : "memory")

#define LDMX4(r0,r1,r2,r3,addr) \
    asm volatile("ldmatrix.sync.aligned.m8n8.x4.shared.b16 {%0,%1,%2,%3}, [%4];" \
        : "=r"(r0),"=r"(r1),"=r"(r2),"=r"(r3) : "r"(addr))

#define MMA16816(d, a, b) \
    asm volatile("mma.sync.aligned.m16n8k16.row.col.f32.bf16.bf16.f32 " \
        "{%0,%1,%2,%3}, {%4,%5,%6,%7}, {%8,%9}, {%0,%1,%2,%3};" \
        : "+f"((d)[0]),"+f"((d)[1]),"+f"((d)[2]),"+f"((d)[3]) \
        : "r"((a)[0]),"r"((a)[1]),"r"((a)[2]),"r"((a)[3]), "r"((b)[0]),"r"((b)[1]))

// ---------------- CSR build (deterministic) ----------------
__global__ void k_zero() {
    int i = blockIdx.x*256 + threadIdx.x;
    if (i < N_) { g_deg[i] = 0; g_cursor[i] = 0; }
}
__global__ void k_count(const int* __restrict__ dstA) {
    int e = blockIdx.x*256 + threadIdx.x;
    if (e < E_) atomicAdd(&g_deg[dstA[e]], 1);
}
__global__ void k_scan() {
    __shared__ int part[1024];
    int t = threadIdx.x;
    int s = 0;
    #pragma unroll
    for (int i = 0; i < 10; i++) { int idx = t*10 + i; if (idx < N_) s += g_deg[idx]; }
    part[t] = s; __syncthreads();
    for (int off = 1; off < 1024; off <<= 1) {
        int v = (t >= off) ? part[t-off] : 0;
        __syncthreads(); part[t] += v; __syncthreads();
    }
    int run = (t == 0) ? 0 : part[t-1];
    #pragma unroll
    for (int i = 0; i < 10; i++) {
        int idx = t*10 + i;
        if (idx < N_) { g_rowptr[idx] = run; run += g_deg[idx]; }
    }
    if (t == 1023) g_rowptr[N_] = part[1023];
}
__global__ void k_fill(const int* __restrict__ dstA) {
    int e = blockIdx.x*256 + threadIdx.x;
    if (e < E_) {
        int d = dstA[e];
        int p = atomicAdd(&g_cursor[d], 1);
        g_tmpeid[g_rowptr[d] + p] = e;
    }
}
// warp rank-sort: one warp per row; edge ids unique -> deterministic order
__global__ void k_sortemit(const int* __restrict__ srcA, const float* __restrict__ kerA) {
    int warp = (blockIdx.x*256 + threadIdx.x) >> 5;
    int l = threadIdx.x & 31;
    if (warp >= N_) return;
    int n = warp;
    int beg = g_rowptr[n], end = g_rowptr[n+1];
    int d = end - beg;
    if (d <= 64) {
        int e0 = (l      < d) ? g_tmpeid[beg + l]      : INT_MAX;
        int e1 = (32 + l < d) ? g_tmpeid[beg + 32 + l] : INT_MAX;
        int r0 = 0, r1 = 0;
        #pragma unroll
        for (int k = 0; k < 32; k++) {
            int v0 = __shfl_sync(0xFFFFFFFFu, e0, k);
            int v1 = __shfl_sync(0xFFFFFFFFu, e1, k);
            r0 += (v0 < e0) + (v1 < e0);
            r1 += (v0 < e1) + (v1 < e1);
        }
        if (l < d)      g_csr[beg + r0] = make_int2(srcA[e0], __float_as_int(kerA[e0]));
        if (32 + l < d) g_csr[beg + r1] = make_int2(srcA[e1], __float_as_int(kerA[e1]));
    } else if (l == 0) {  // fallback: degree ~Poisson(16); effectively never
        for (int i = 1; i < d; i++) {
            int key = g_tmpeid[beg+i]; int j = i-1;
            while (j >= 0 && g_tmpeid[beg+j] > key) { g_tmpeid[beg+j+1] = g_tmpeid[beg+j]; j--; }
            g_tmpeid[beg+j+1] = key;
        }
        for (int i = 0; i < d; i++) {
            int e = g_tmpeid[beg+i];
            g_csr[beg+i] = make_int2(srcA[e], __float_as_int(kerA[e]));
        }
    }
}

// ---------------- conversions (merged weights + concat-split) ----------------
__device__ __forceinline__ void split_bf16(float a, __nv_bfloat16& h, __nv_bfloat16& l) {
    h = __float2bfloat16(a);
    l = __float2bfloat16(a - __bfloat162float(h));
}
#define W1SZ (NC1*128)
#define W2SZ (NC2*64)
#define WTOT (W1SZ + W2SZ)
__global__ void k_prep(const float* __restrict__ W_ru, const float* __restrict__ W_c,
                       const float* __restrict__ inputs, const float* __restrict__ hx) {
    int i = blockIdx.x*256 + threadIdx.x;
    if (i < W1SZ) {
        int c = i / 128, k = i & 127;
        float v;
        if (c < 384) { int vv = c >> 7, o = c & 127; v = W_ru[(vv*128 + k)*128 + o]; }
        else { int c2 = c - 384; int vv = c2 >> 6, o = c2 & 63;
               v = (k < 64) ? W_c[(vv*128 + k)*64 + o] : 0.f; }
        split_bf16(v, g_W1h[i], g_W1l[i]);
    } else if (i < WTOT) {
        int j = i - W1SZ;
        int c = j / 64, k = j & 63;
        int vv = c >> 6, o = c & 63;
        float v = W_c[(vv*128 + 64 + k)*64 + o];
        split_bf16(v, g_W2h[j], g_W2l[j]);
    } else if (i < WTOT + M_*128) {
        int j = i - WTOT;
        int m = j >> 7, k = j & 127;
        float a = (k < 64) ? inputs[m*64 + k] : hx[m*64 + (k-64)];
        split_bf16(a, g_Xh[j], g_Xl[j]);
    }
}

// ---------------- HMMA GEMM (mma.sync bf16 hi/lo split, fp32 accum) ----------------
template<int MODE>
__global__ void __launch_bounds__(128) k_mma_gemm() {
    constexpr int KD   = (MODE==1) ? 128 : 64;
    constexpr int CH   = KD/64;
    constexpr int NCH  = 3*CH;
    constexpr int ABYT = 128*64*2;
    constexpr int BBYT = 64*64*2;
    constexpr int BUF  = ABYT + BBYT;      // 24576; x2 = 49152 (default max)

    extern __shared__ char dsm[];
    const uint32_t sbase = smem_u32(dsm);

    const int t = threadIdx.x;
    const int w = t >> 5, l = t & 31;
    const int m0 = blockIdx.x*128, cb = blockIdx.y*64;

    const __nv_bfloat16* A0 = (MODE==1) ? g_Xh  : g_gh;
    const __nv_bfloat16* A1 = (MODE==1) ? g_Xl  : g_gl;
    const __nv_bfloat16* B0 = (MODE==1) ? g_W1h : g_W2h;
    const __nv_bfloat16* B1 = (MODE==1) ? g_W1l : g_W2l;

    float acc[2][8][4];
    #pragma unroll
    for (int i = 0; i < 2; i++)
        #pragma unroll
        for (int j = 0; j < 8; j++)
            #pragma unroll
            for (int k = 0; k < 4; k++) acc[i][j][k] = 0.f;

    const int jm = l >> 3, r = l & 7;
    const int a_row_off = (jm & 1)*8 + r;
    const int a_kcj     = jm >> 1;
    const int b_row_off = (jm >> 1)*8 + r;
    const int b_kcj     = jm & 1;

    auto load_chunk = [&](int ci, int buf) {
        int p = ci / CH, h = ci % CH;
        const __nv_bfloat16* Ap = (p == 2) ? A1 : A0;
        const __nv_bfloat16* Bp = (p == 1) ? B1 : B0;
        uint32_t ab = sbase + buf*BUF;
        uint32_t bb = ab + ABYT;
        int koff = h*64;
        #pragma unroll
        for (int it = 0; it < 8; it++) {
            int idx = it*128 + t;
            int row = idx >> 3, c = idx & 7;
            int gm = m0 + row;
            bool ok = gm < M_;
            const void* src = Ap + (size_t)(ok ? gm : m0)*KD + koff + c*8;
            cp16(ab + row*128 + ((c ^ (row & 7))*16), src, ok);
        }
        #pragma unroll
        for (int it = 0; it < 4; it++) {
            int idx = it*128 + t;
            int row = idx >> 3, c = idx & 7;
            const void* src = Bp + (size_t)(cb + row)*KD + koff + c*8;
            cp16(bb + row*128 + ((c ^ (row & 7))*16), src, true);
        }
        CP_COMMIT();
    };

    load_chunk(0, 0);
    for (int i = 0; i < NCH; i++) {
        if (i + 1 < NCH) { load_chunk(i+1, (i+1)&1); CP_WAIT(1); }
        else             { CP_WAIT(0); }
        __syncthreads();
        uint32_t ab = sbase + (i&1)*BUF;
        uint32_t bb = ab + ABYT;
        #pragma unroll
        for (int ks = 0; ks < 4; ks++) {
            uint32_t af[2][4];
            #pragma unroll
            for (int mt = 0; mt < 2; mt++) {
                int row = w*32 + mt*16 + a_row_off;
                uint32_t addr = ab + row*128 + (((ks*2 + a_kcj) ^ r) * 16);
                LDMX4(af[mt][0], af[mt][1], af[mt][2], af[mt][3], addr);
            }
            uint32_t bf[8][2];
            #pragma unroll
            for (int np = 0; np < 4; np++) {
                int row = np*16 + b_row_off;
                uint32_t addr = bb + row*128 + (((ks*2 + b_kcj) ^ r) * 16);
                uint32_t q0, q1, q2, q3;
                LDMX4(q0, q1, q2, q3, addr);
                bf[2*np][0]   = q0; bf[2*np][1]   = q1;
                bf[2*np+1][0] = q2; bf[2*np+1][1] = q3;
            }
            #pragma unroll
            for (int mt = 0; mt < 2; mt++)
                #pragma unroll
                for (int nt = 0; nt < 8; nt++)
                    MMA16816(acc[mt][nt], af[mt], bf[nt]);
        }
        __syncthreads();
    }

    // epilogue: fp32 float2 stores to view buffers
    float* dstBuf; int dstride;
    if (MODE == 1) {
        if (cb < 384) { dstBuf = g_Pru[cb >> 7] + (cb & 127); dstride = 128; }
        else          { dstBuf = g_Qc[(cb - 384) >> 6];       dstride = 64;  }
    } else {
        dstBuf = g_Qc[blockIdx.y]; dstride = 64;
    }
    const int g = l >> 2, t4 = l & 3;
    #pragma unroll
    for (int mt = 0; mt < 2; mt++) {
        int row0 = m0 + w*32 + mt*16 + g;
        #pragma unroll
        for (int nt = 0; nt < 8; nt++) {
            int col = nt*8 + t4*2;
            #pragma unroll
            for (int half = 0; half < 2; half++) {
                int row = row0 + half*8;
                if (row >= M_) continue;
                float2 v = make_float2(acc[mt][nt][half*2], acc[mt][nt][half*2+1]);
                float* p = dstBuf + (size_t)row*dstride + col;
                if (MODE == 2) { float2 o = *(float2*)p; v.x += o.x; v.y += o.y; }
                *(float2*)p = v;
            }
        }
    }
}

// ---------------- SpMM with shuffle-staged CSR + fused epilogues ----------------
// O[m] = Add[m] + sum_{e in row n(m)} ker_e * S[bN + src_e]
// EPI: 0 = plain fp32 store to OID; 1 = GRU gate epilogue; 2 = final-output epilogue.
template<int COLS, int SID, int AID, int OID, int EPI>
__global__ void __launch_bounds__(256) k_spmm(const float* __restrict__ hx,
                                              const float* __restrict__ bias,
                                              float* __restrict__ outp) {
    const float* __restrict__ S   = sel_buf<SID>();
    const float* __restrict__ Add = sel_buf<AID>();
    constexpr int GS  = COLS/4;     // 32 (ru) or 16 (c) threads per row
    constexpr int GPB = 256/GS;
    // grids are exact (M_ divisible): every thread has a valid row -> warp-synchronous safe
    int m  = blockIdx.x*GPB + threadIdx.x/GS;
    int gl = threadIdx.x & (GS-1);
    int c  = gl*4;
    int n  = m % N_;
    int bN = m - n;
    int beg = g_rowptr[n];
    int d   = g_rowptr[n+1] - beg;
    const unsigned FULL = 0xFFFFFFFFu;
    const int sb = (GS == 32) ? 0 : (threadIdx.x & 16);  // shuffle source base within warp
    int dmax = __reduce_max_sync(FULL, d);               // warp-uniform batch count
    float a0 = 0.f, a1 = 0.f, a2 = 0.f, a3 = 0.f;
    for (int b0 = 0; b0 < dmax; b0 += GS) {
        int idx = b0 + gl;
        int2 e = (idx < d) ? __ldg(&g_csr[beg + idx]) : make_int2(0, 0);
        int cntw = min(GS, dmax - b0);   // warp-uniform
        int cnt  = min(GS, d - b0);      // per-group (may be <= 0)
        #pragma unroll 4
        for (int j = 0; j < cntw; j++) {
            int   src = __shfl_sync(FULL, e.x, sb + j);
            float kv  = __int_as_float(__shfl_sync(FULL, e.y, sb + j));
            if (j < cnt) {
                const float4 v = __ldg((const float4*)&S[(size_t)(bN + src)*COLS + c]);
                a0 = fmaf(kv, v.x, a0);
                a1 = fmaf(kv, v.y, a1);
                a2 = fmaf(kv, v.z, a2);
                a3 = fmaf(kv, v.w, a3);
            }
        }
    }
    const float4 ad = __ldg((const float4*)&Add[(size_t)m*COLS + c]);
    a0 += ad.x; a1 += ad.y; a2 += ad.z; a3 += ad.w;

    if constexpr (EPI == 0) {
        float* O = sel_buf<OID>();
        *(float4*)&O[(size_t)m*COLS + c] = make_float4(a0, a1, a2, a3);
    } else if constexpr (EPI == 1) {
        // gate: a = ru pre-activation col c..c+3 of [M][128]; bias = b_ru[128]
        const float4 bb = __ldg((const float4*)&bias[c]);
        float s0 = 1.f/(1.f + __expf(-(a0 + bb.x)));
        float s1 = 1.f/(1.f + __expf(-(a1 + bb.y)));
        float s2 = 1.f/(1.f + __expf(-(a2 + bb.z)));
        float s3 = 1.f/(1.f + __expf(-(a3 + bb.w)));
        if (c < 64) {   // r half: g = r*hx, bf16 hi/lo split
            const float4 h = __ldg((const float4*)&hx[(size_t)m*64 + c]);
            float g0 = s0*h.x, g1 = s1*h.y, g2 = s2*h.z, g3 = s3*h.w;
            __nv_bfloat16 h0,h1,h2,h3,l0,l1,l2,l3;
            split_bf16(g0,h0,l0); split_bf16(g1,h1,l1);
            split_bf16(g2,h2,l2); split_bf16(g3,h3,l3);
            __nv_bfloat162 ph0 = __halves2bfloat162(h0,h1), ph1 = __halves2bfloat162(h2,h3);
            __nv_bfloat162 pl0 = __halves2bfloat162(l0,l1), pl1 = __halves2bfloat162(l2,l3);
            uint2 uh, ul;
            uh.x = *(uint32_t*)&ph0; uh.y = *(uint32_t*)&ph1;
            ul.x = *(uint32_t*)&pl0; ul.y = *(uint32_t*)&pl1;
            *(uint2*)&g_gh[(size_t)m*64 + c] = uh;
            *(uint2*)&g_gl[(size_t)m*64 + c] = ul;
        } else {        // u half
            *(float4*)&g_U[(size_t)m*64 + (c - 64)] = make_float4(s0, s1, s2, s3);
        }
    } else {
        // final: a = c pre-activation col c..c+3 of [M][64]; bias = b_c[64]
        const float4 bb = __ldg((const float4*)&bias[c]);
        float c0 = tanhf(a0 + bb.x);
        float c1 = tanhf(a1 + bb.y);
        float c2 = tanhf(a2 + bb.z);
        float c3 = tanhf(a3 + bb.w);
        const float4 u = __ldg((const float4*)&g_U[(size_t)m*64 + c]);
        const float4 h = __ldg((const float4*)&hx[(size_t)m*64 + c]);
        float4 o;
        o.x = u.x*h.x + (1.f - u.x)*c0;
        o.y = u.y*h.y + (1.f - u.y)*c1;
        o.z = u.z*h.z + (1.f - u.z)*c2;
        o.w = u.w*h.w + (1.f - u.w)*c3;
        *(float4*)&outp[(size_t)m*64 + c] = o;
    }
}

// ---------------- launch: fork-join dual-stream (graph-capture legal) ----------------
extern "C" void kernel_launch(void* const* d_in, const int* in_sizes, int n_in,
                              void* d_out, int out_size) {
    const float* inputs = (const float*)d_in[0];
    const float* hx     = (const float*)d_in[1];
    const int*   sidx   = (const int*)  d_in[2];
    const float* ker    = (const float*)d_in[3];
    const float* W_ru   = (const float*)d_in[4];
    const float* b_ru   = (const float*)d_in[5];
    const float* W_c    = (const float*)d_in[6];
    const float* b_c    = (const float*)d_in[7];
    float* out = (float*)d_out;
    const int* srcA = sidx;
    const int* dstA = sidx + E_;

    const int DSM = 2*(128*64*2 + 64*64*2);   // 49152 = default dynamic smem max

    static cudaStream_t s2 = nullptr;
    static cudaEvent_t evFork = nullptr, evJoin = nullptr;
    if (s2 == nullptr) {
        cudaStreamCreateWithFlags(&s2, cudaStreamNonBlocking);
        cudaEventCreateWithFlags(&evFork, cudaEventDisableTiming);
        cudaEventCreateWithFlags(&evJoin, cudaEventDisableTiming);
    }

    // fork: CSR build chain on s2
    cudaEventRecord(evFork, 0);
    cudaStreamWaitEvent(s2, evFork, 0);
    k_zero    <<<(N_ + 255)/256, 256, 0, s2>>>();
    k_count   <<<(E_ + 255)/256, 256, 0, s2>>>(dstA);
    k_scan    <<<1, 1024, 0, s2>>>();
    k_fill    <<<(E_ + 255)/256, 256, 0, s2>>>(dstA);
    k_sortemit<<<(N_*32 + 255)/256, 256, 0, s2>>>(srcA, ker);
    cudaEventRecord(evJoin, s2);

    // main chain: conversions + GEMM1 (independent of CSR)
    k_prep<<<(WTOT + M_*128 + 255)/256, 256>>>(W_ru, W_c, inputs, hx);
    k_mma_gemm<1><<<dim3(MTILE, NC1/64), 128, DSM>>>();

    // join: SpMM needs both CSR and GEMM1
    cudaStreamWaitEvent(0, evJoin, 0);

    // ru sparse: Pru1 += A*Pru2 ; fused-gate pass: sigmoid(P0 + A*Pru1 + b_ru)
    k_spmm<128, 2, 1, 1, 0><<<M_/8,  256>>>(nullptr, nullptr, nullptr);
    k_spmm<128, 1, 0, 0, 1><<<M_/8,  256>>>(hx, b_ru, nullptr);

    // GEMM2 (HMMA): Qc[0..2] += g @ W2
    k_mma_gemm<2><<<dim3(MTILE, NC2/64), 128, DSM>>>();

    // c sparse: Qc1 += A*Qc2 ; fused-final pass: out = u*hx + (1-u)*tanh(Qc0 + A*Qc1 + b_c)
    k_spmm<64, 5, 4, 4, 0><<<M_/16, 256>>>(nullptr, nullptr, nullptr);
    k_spmm<64, 4, 3, 0, 2><<<M_/16, 256>>>(hx, b_c, out);
}

// round 11
// speedup vs baseline: 1.0277x; 1.0277x over previous
#include <cuda_runtime.h>
#include <cuda_bf16.h>
#include <math.h>
#include <cstdint>
#include <limits.h>

// ---------------- problem constants ----------------
#define B_    4
#define N_    10000
#define E_    160000
#define M_    (B_*N_)        // 40000 rows (m = b*N + n)
#define NC1   576            // GEMM1 cols: 3*128 (ru views) + 3*64 (c input views)
#define NC2   192            // GEMM2 cols: 3*64 (c hidden views)
#define MTILE ((M_ + 127)/128)   // 313 row tiles

// ---------------- scratch (static device globals; no runtime alloc) ----------------
__device__ __nv_bfloat16 g_Xh[M_*128];   // hi(concat(inputs,hx))
__device__ __nv_bfloat16 g_Xl[M_*128];   // lo part
__device__ __nv_bfloat16 g_gh[M_*64];    // hi(r*hx)
__device__ __nv_bfloat16 g_gl[M_*64];
__device__ __nv_bfloat16 g_W1h[NC1*128]; // GEMM1 weights, [c][k]
__device__ __nv_bfloat16 g_W1l[NC1*128];
__device__ __nv_bfloat16 g_W2h[NC2*64];
__device__ __nv_bfloat16 g_W2l[NC2*64];
__device__ float g_Pru[3][M_*128];       // ru fp32 views
__device__ float g_Qc [3][M_*64];        // c  fp32 views
__device__ float g_U  [M_*64];           // u gate
__device__ int   g_deg[N_];
__device__ int   g_rowptr[N_+1];
__device__ int   g_cursor[N_];
__device__ int   g_tmpeid[E_];
__device__ int2  g_csr[E_];              // packed (src, ker bits)

// compile-time scratch-buffer selector: 0..2 -> g_Pru[v], 3..5 -> g_Qc[v-3]
template<int ID>
__device__ __forceinline__ float* sel_buf() {
    if constexpr (ID < 3) return g_Pru[ID];
    else                  return g_Qc[ID-3];
}

// ---------------- PTX helpers (baseline ISA only) ----------------
__device__ __forceinline__ uint32_t smem_u32(const void* p) {
    uint32_t a;
    asm("{ .reg .u64 t; cvta.to.shared.u64 t, %1; cvt.u32.u64 %0, t; }" : "=r"(a) : "l"(p));
    return a;
}
__device__ __forceinline__ void cp16(uint32_t dst, const void* src, bool full) {
    int sz = full ? 16 : 0;
    asm volatile("cp.async.cg.shared.global [%0], [%1], 16, %2;"
                 :: "r"(dst), "l"(src), "r"(sz) : "memory");
}
#define CP_COMMIT()  asm volatile("cp.async.commit_group;" ::: "memory")
#define CP_WAIT(n)   asm volatile("cp.async.wait_group %0;" :: "n"(n) : "memory")

#define LDMX4(r0,r1,r2,r3,addr) \
    asm volatile("ldmatrix.sync.aligned.m8n8.x4.shared.b16 {%0,%1,%2,%3}, [%4];" \
        : "=r"(r0),"=r"(r1),"=r"(r2),"=r"(r3) : "r"(addr))

#define MMA16816(d, a, b) \
    asm volatile("mma.sync.aligned.m16n8k16.row.col.f32.bf16.bf16.f32 " \
        "{%0,%1,%2,%3}, {%4,%5,%6,%7}, {%8,%9}, {%0,%1,%2,%3};" \
        : "+f"((d)[0]),"+f"((d)[1]),"+f"((d)[2]),"+f"((d)[3]) \
        : "r"((a)[0]),"r"((a)[1]),"r"((a)[2]),"r"((a)[3]), "r"((b)[0]),"r"((b)[1]))

// ---------------- CSR build (deterministic) ----------------
__global__ void k_zero() {
    int i = blockIdx.x*256 + threadIdx.x;
    if (i < N_) { g_deg[i] = 0; g_cursor[i] = 0; }
}
__global__ void k_count(const int* __restrict__ dstA) {
    int e = blockIdx.x*256 + threadIdx.x;
    if (e < E_) atomicAdd(&g_deg[dstA[e]], 1);
}
__global__ void k_scan() {
    __shared__ int part[1024];
    int t = threadIdx.x;
    int s = 0;
    #pragma unroll
    for (int i = 0; i < 10; i++) { int idx = t*10 + i; if (idx < N_) s += g_deg[idx]; }
    part[t] = s; __syncthreads();
    for (int off = 1; off < 1024; off <<= 1) {
        int v = (t >= off) ? part[t-off] : 0;
        __syncthreads(); part[t] += v; __syncthreads();
    }
    int run = (t == 0) ? 0 : part[t-1];
    #pragma unroll
    for (int i = 0; i < 10; i++) {
        int idx = t*10 + i;
        if (idx < N_) { g_rowptr[idx] = run; run += g_deg[idx]; }
    }
    if (t == 1023) g_rowptr[N_] = part[1023];
}
__global__ void k_fill(const int* __restrict__ dstA) {
    int e = blockIdx.x*256 + threadIdx.x;
    if (e < E_) {
        int d = dstA[e];
        int p = atomicAdd(&g_cursor[d], 1);
        g_tmpeid[g_rowptr[d] + p] = e;
    }
}
// warp rank-sort: one warp per row; edge ids unique -> deterministic order
__global__ void k_sortemit(const int* __restrict__ srcA, const float* __restrict__ kerA) {
    int warp = (blockIdx.x*256 + threadIdx.x) >> 5;
    int l = threadIdx.x & 31;
    if (warp >= N_) return;
    int n = warp;
    int beg = g_rowptr[n], end = g_rowptr[n+1];
    int d = end - beg;
    if (d <= 64) {
        int e0 = (l      < d) ? g_tmpeid[beg + l]      : INT_MAX;
        int e1 = (32 + l < d) ? g_tmpeid[beg + 32 + l] : INT_MAX;
        int r0 = 0, r1 = 0;
        #pragma unroll
        for (int k = 0; k < 32; k++) {
            int v0 = __shfl_sync(0xFFFFFFFFu, e0, k);
            int v1 = __shfl_sync(0xFFFFFFFFu, e1, k);
            r0 += (v0 < e0) + (v1 < e0);
            r1 += (v0 < e1) + (v1 < e1);
        }
        if (l < d)      g_csr[beg + r0] = make_int2(srcA[e0], __float_as_int(kerA[e0]));
        if (32 + l < d) g_csr[beg + r1] = make_int2(srcA[e1], __float_as_int(kerA[e1]));
    } else if (l == 0) {  // fallback: degree ~Poisson(16); effectively never
        for (int i = 1; i < d; i++) {
            int key = g_tmpeid[beg+i]; int j = i-1;
            while (j >= 0 && g_tmpeid[beg+j] > key) { g_tmpeid[beg+j+1] = g_tmpeid[beg+j]; j--; }
            g_tmpeid[beg+j+1] = key;
        }
        for (int i = 0; i < d; i++) {
            int e = g_tmpeid[beg+i];
            g_csr[beg+i] = make_int2(srcA[e], __float_as_int(kerA[e]));
        }
    }
}

// ---------------- conversions (merged weights + concat-split) ----------------
__device__ __forceinline__ void split_bf16(float a, __nv_bfloat16& h, __nv_bfloat16& l) {
    h = __float2bfloat16(a);
    l = __float2bfloat16(a - __bfloat162float(h));
}
#define W1SZ (NC1*128)
#define W2SZ (NC2*64)
#define WTOT (W1SZ + W2SZ)
__global__ void k_prep(const float* __restrict__ W_ru, const float* __restrict__ W_c,
                       const float* __restrict__ inputs, const float* __restrict__ hx) {
    int i = blockIdx.x*256 + threadIdx.x;
    if (i < W1SZ) {
        int c = i / 128, k = i & 127;
        float v;
        if (c < 384) { int vv = c >> 7, o = c & 127; v = W_ru[(vv*128 + k)*128 + o]; }
        else { int c2 = c - 384; int vv = c2 >> 6, o = c2 & 63;
               v = (k < 64) ? W_c[(vv*128 + k)*64 + o] : 0.f; }
        split_bf16(v, g_W1h[i], g_W1l[i]);
    } else if (i < WTOT) {
        int j = i - W1SZ;
        int c = j / 64, k = j & 63;
        int vv = c >> 6, o = c & 63;
        float v = W_c[(vv*128 + 64 + k)*64 + o];
        split_bf16(v, g_W2h[j], g_W2l[j]);
    } else if (i < WTOT + M_*128) {
        int j = i - WTOT;
        int m = j >> 7, k = j & 127;
        float a = (k < 64) ? inputs[m*64 + k] : hx[m*64 + (k-64)];
        split_bf16(a, g_Xh[j], g_Xl[j]);
    }
}

// ---------------- HMMA GEMM (mma.sync bf16 hi/lo split, fp32 accum) ----------------
template<int MODE>
__global__ void __launch_bounds__(128) k_mma_gemm() {
    constexpr int KD   = (MODE==1) ? 128 : 64;
    constexpr int CH   = KD/64;
    constexpr int NCH  = 3*CH;
    constexpr int ABYT = 128*64*2;
    constexpr int BBYT = 64*64*2;
    constexpr int BUF  = ABYT + BBYT;      // 24576; x2 = 49152 (default max)

    extern __shared__ char dsm[];
    const uint32_t sbase = smem_u32(dsm);

    const int t = threadIdx.x;
    const int w = t >> 5, l = t & 31;
    const int m0 = blockIdx.x*128, cb = blockIdx.y*64;

    const __nv_bfloat16* A0 = (MODE==1) ? g_Xh  : g_gh;
    const __nv_bfloat16* A1 = (MODE==1) ? g_Xl  : g_gl;
    const __nv_bfloat16* B0 = (MODE==1) ? g_W1h : g_W2h;
    const __nv_bfloat16* B1 = (MODE==1) ? g_W1l : g_W2l;

    float acc[2][8][4];
    #pragma unroll
    for (int i = 0; i < 2; i++)
        #pragma unroll
        for (int j = 0; j < 8; j++)
            #pragma unroll
            for (int k = 0; k < 4; k++) acc[i][j][k] = 0.f;

    const int jm = l >> 3, r = l & 7;
    const int a_row_off = (jm & 1)*8 + r;
    const int a_kcj     = jm >> 1;
    const int b_row_off = (jm >> 1)*8 + r;
    const int b_kcj     = jm & 1;

    auto load_chunk = [&](int ci, int buf) {
        int p = ci / CH, h = ci % CH;
        const __nv_bfloat16* Ap = (p == 2) ? A1 : A0;
        const __nv_bfloat16* Bp = (p == 1) ? B1 : B0;
        uint32_t ab = sbase + buf*BUF;
        uint32_t bb = ab + ABYT;
        int koff = h*64;
        #pragma unroll
        for (int it = 0; it < 8; it++) {
            int idx = it*128 + t;
            int row = idx >> 3, c = idx & 7;
            int gm = m0 + row;
            bool ok = gm < M_;
            const void* src = Ap + (size_t)(ok ? gm : m0)*KD + koff + c*8;
            cp16(ab + row*128 + ((c ^ (row & 7))*16), src, ok);
        }
        #pragma unroll
        for (int it = 0; it < 4; it++) {
            int idx = it*128 + t;
            int row = idx >> 3, c = idx & 7;
            const void* src = Bp + (size_t)(cb + row)*KD + koff + c*8;
            cp16(bb + row*128 + ((c ^ (row & 7))*16), src, true);
        }
        CP_COMMIT();
    };

    load_chunk(0, 0);
    for (int i = 0; i < NCH; i++) {
        if (i + 1 < NCH) { load_chunk(i+1, (i+1)&1); CP_WAIT(1); }
        else             { CP_WAIT(0); }
        __syncthreads();
        uint32_t ab = sbase + (i&1)*BUF;
        uint32_t bb = ab + ABYT;
        #pragma unroll
        for (int ks = 0; ks < 4; ks++) {
            uint32_t af[2][4];
            #pragma unroll
            for (int mt = 0; mt < 2; mt++) {
                int row = w*32 + mt*16 + a_row_off;
                uint32_t addr = ab + row*128 + (((ks*2 + a_kcj) ^ r) * 16);
                LDMX4(af[mt][0], af[mt][1], af[mt][2], af[mt][3], addr);
            }
            uint32_t bf[8][2];
            #pragma unroll
            for (int np = 0; np < 4; np++) {
                int row = np*16 + b_row_off;
                uint32_t addr = bb + row*128 + (((ks*2 + b_kcj) ^ r) * 16);
                uint32_t q0, q1, q2, q3;
                LDMX4(q0, q1, q2, q3, addr);
                bf[2*np][0]   = q0; bf[2*np][1]   = q1;
                bf[2*np+1][0] = q2; bf[2*np+1][1] = q3;
            }
            #pragma unroll
            for (int mt = 0; mt < 2; mt++)
                #pragma unroll
                for (int nt = 0; nt < 8; nt++)
                    MMA16816(acc[mt][nt], af[mt], bf[nt]);
        }
        __syncthreads();
    }

    // epilogue: fp32 float2 stores to view buffers
    float* dstBuf; int dstride;
    if (MODE == 1) {
        if (cb < 384) { dstBuf = g_Pru[cb >> 7] + (cb & 127); dstride = 128; }
        else          { dstBuf = g_Qc[(cb - 384) >> 6];       dstride = 64;  }
    } else {
        dstBuf = g_Qc[blockIdx.y]; dstride = 64;
    }
    const int g = l >> 2, t4 = l & 3;
    #pragma unroll
    for (int mt = 0; mt < 2; mt++) {
        int row0 = m0 + w*32 + mt*16 + g;
        #pragma unroll
        for (int nt = 0; nt < 8; nt++) {
            int col = nt*8 + t4*2;
            #pragma unroll
            for (int half = 0; half < 2; half++) {
                int row = row0 + half*8;
                if (row >= M_) continue;
                float2 v = make_float2(acc[mt][nt][half*2], acc[mt][nt][half*2+1]);
                float* p = dstBuf + (size_t)row*dstride + col;
                if (MODE == 2) { float2 o = *(float2*)p; v.x += o.x; v.y += o.y; }
                *(float2*)p = v;
            }
        }
    }
}

// ---------------- SpMM (64-col groups) with shuffle-staged CSR + fused epilogues ----
// O[m, COFF..COFF+63] = Add[m, same] + sum_e ker_e * S[bN+src_e, same]; row stride RS.
// EPI: 0 = plain store; 1 = r-gate (sigmoid -> g bf16 split); 2 = final out; 3 = u-gate.
template<int RS, int COFF, int SID, int AID, int OID, int EPI>
__global__ void __launch_bounds__(256) k_spmm(const float* __restrict__ hx,
                                              const float* __restrict__ bias,
                                              float* __restrict__ outp) {
    const float* __restrict__ S   = sel_buf<SID>();
    const float* __restrict__ Add = sel_buf<AID>();
    constexpr int GS = 16;          // 16 threads x float4 = 64 cols
    // grids exact (M_ % 16 == 0): every thread valid -> warp-synchronous safe
    int m  = blockIdx.x*16 + threadIdx.x/GS;
    int gl = threadIdx.x & (GS-1);
    int c  = COFF + gl*4;
    int n  = m % N_;
    int bN = m - n;
    int beg = g_rowptr[n];
    int d   = g_rowptr[n+1] - beg;
    const unsigned FULL = 0xFFFFFFFFu;
    const int sb = threadIdx.x & 16;                 // shuffle source base (half-warp)
    int dmax = __reduce_max_sync(FULL, d);           // warp-uniform batch count
    float a0 = 0.f, a1 = 0.f, a2 = 0.f, a3 = 0.f;
    for (int b0 = 0; b0 < dmax; b0 += GS) {
        int idx = b0 + gl;
        int2 e = (idx < d) ? __ldg(&g_csr[beg + idx]) : make_int2(0, 0);
        int cntw = min(GS, dmax - b0);   // warp-uniform
        int cnt  = min(GS, d - b0);      // per-group (may be <= 0)
        #pragma unroll 4
        for (int j = 0; j < cntw; j++) {
            int   src = __shfl_sync(FULL, e.x, sb + j);
            float kv  = __int_as_float(__shfl_sync(FULL, e.y, sb + j));
            if (j < cnt) {
                const float4 v = __ldg((const float4*)&S[(size_t)(bN + src)*RS + c]);
                a0 = fmaf(kv, v.x, a0);
                a1 = fmaf(kv, v.y, a1);
                a2 = fmaf(kv, v.z, a2);
                a3 = fmaf(kv, v.w, a3);
            }
        }
    }
    const float4 ad = __ldg((const float4*)&Add[(size_t)m*RS + c]);
    a0 += ad.x; a1 += ad.y; a2 += ad.z; a3 += ad.w;

    if constexpr (EPI == 0) {
        float* O = sel_buf<OID>();
        *(float4*)&O[(size_t)m*RS + c] = make_float4(a0, a1, a2, a3);
    } else if constexpr (EPI == 1) {
        // r gate: c in [0,64); bias = b_ru; g = sigmoid(a+b)*hx, bf16 hi/lo split
        const float4 bb = __ldg((const float4*)&bias[c]);
        float s0 = 1.f/(1.f + __expf(-(a0 + bb.x)));
        float s1 = 1.f/(1.f + __expf(-(a1 + bb.y)));
        float s2 = 1.f/(1.f + __expf(-(a2 + bb.z)));
        float s3 = 1.f/(1.f + __expf(-(a3 + bb.w)));
        const float4 h = __ldg((const float4*)&hx[(size_t)m*64 + c]);
        float g0 = s0*h.x, g1 = s1*h.y, g2 = s2*h.z, g3 = s3*h.w;
        __nv_bfloat16 h0,h1,h2,h3,l0,l1,l2,l3;
        split_bf16(g0,h0,l0); split_bf16(g1,h1,l1);
        split_bf16(g2,h2,l2); split_bf16(g3,h3,l3);
        __nv_bfloat162 ph0 = __halves2bfloat162(h0,h1), ph1 = __halves2bfloat162(h2,h3);
        __nv_bfloat162 pl0 = __halves2bfloat162(l0,l1), pl1 = __halves2bfloat162(l2,l3);
        uint2 uh, ul;
        uh.x = *(uint32_t*)&ph0; uh.y = *(uint32_t*)&ph1;
        ul.x = *(uint32_t*)&pl0; ul.y = *(uint32_t*)&pl1;
        *(uint2*)&g_gh[(size_t)m*64 + c] = uh;
        *(uint2*)&g_gl[(size_t)m*64 + c] = ul;
    } else if constexpr (EPI == 3) {
        // u gate: c in [64,128); bias = b_ru (indexed at c); write U at c-64
        const float4 bb = __ldg((const float4*)&bias[c]);
        float s0 = 1.f/(1.f + __expf(-(a0 + bb.x)));
        float s1 = 1.f/(1.f + __expf(-(a1 + bb.y)));
        float s2 = 1.f/(1.f + __expf(-(a2 + bb.z)));
        float s3 = 1.f/(1.f + __expf(-(a3 + bb.w)));
        *(float4*)&g_U[(size_t)m*64 + (c - 64)] = make_float4(s0, s1, s2, s3);
    } else {
        // final: c in [0,64); bias = b_c
        const float4 bb = __ldg((const float4*)&bias[c]);
        float c0 = tanhf(a0 + bb.x);
        float c1 = tanhf(a1 + bb.y);
        float c2 = tanhf(a2 + bb.z);
        float c3 = tanhf(a3 + bb.w);
        const float4 u = __ldg((const float4*)&g_U[(size_t)m*64 + c]);
        const float4 h = __ldg((const float4*)&hx[(size_t)m*64 + c]);
        float4 o;
        o.x = u.x*h.x + (1.f - u.x)*c0;
        o.y = u.y*h.y + (1.f - u.y)*c1;
        o.z = u.z*h.z + (1.f - u.z)*c2;
        o.w = u.w*h.w + (1.f - u.w)*c3;
        *(float4*)&outp[(size_t)m*64 + c] = o;
    }
}

// ---------------- launch: dual-stream with u-path overlapped (graph-capture legal) ----
extern "C" void kernel_launch(void* const* d_in, const int* in_sizes, int n_in,
                              void* d_out, int out_size) {
    const float* inputs = (const float*)d_in[0];
    const float* hx     = (const float*)d_in[1];
    const int*   sidx   = (const int*)  d_in[2];
    const float* ker    = (const float*)d_in[3];
    const float* W_ru   = (const float*)d_in[4];
    const float* b_ru   = (const float*)d_in[5];
    const float* W_c    = (const float*)d_in[6];
    const float* b_c    = (const float*)d_in[7];
    float* out = (float*)d_out;
    const int* srcA = sidx;
    const int* dstA = sidx + E_;

    const int DSM = 2*(128*64*2 + 64*64*2);   // 49152 = default dynamic smem max

    static cudaStream_t s2 = nullptr;
    static cudaEvent_t evFork = nullptr, evJoin = nullptr, evG1 = nullptr, evU = nullptr;
    if (s2 == nullptr) {
        cudaStreamCreateWithFlags(&s2, cudaStreamNonBlocking);
        cudaEventCreateWithFlags(&evFork, cudaEventDisableTiming);
        cudaEventCreateWithFlags(&evJoin, cudaEventDisableTiming);
        cudaEventCreateWithFlags(&evG1,   cudaEventDisableTiming);
        cudaEventCreateWithFlags(&evU,    cudaEventDisableTiming);
    }

    // fork: CSR build chain on s2
    cudaEventRecord(evFork, 0);
    cudaStreamWaitEvent(s2, evFork, 0);
    k_zero    <<<(N_ + 255)/256, 256, 0, s2>>>();
    k_count   <<<(E_ + 255)/256, 256, 0, s2>>>(dstA);
    k_scan    <<<1, 1024, 0, s2>>>();
    k_fill    <<<(E_ + 255)/256, 256, 0, s2>>>(dstA);
    k_sortemit<<<(N_*32 + 255)/256, 256, 0, s2>>>(srcA, ker);
    cudaEventRecord(evJoin, s2);

    // main chain: conversions + GEMM1 (independent of CSR)
    k_prep<<<(WTOT + M_*128 + 255)/256, 256>>>(W_ru, W_c, inputs, hx);
    k_mma_gemm<1><<<dim3(MTILE, NC1/64), 128, DSM>>>();
    cudaEventRecord(evG1, 0);

    // s2: u-half ru passes (needs CSR [s2-ordered] + GEMM1 [evG1]); writes g_U
    cudaStreamWaitEvent(s2, evG1, 0);
    k_spmm<128, 64, 2, 1, 1, 0><<<M_/16, 256, 0, s2>>>(nullptr, nullptr, nullptr);
    k_spmm<128, 64, 1, 0, 0, 3><<<M_/16, 256, 0, s2>>>(nullptr, b_ru, nullptr);
    cudaEventRecord(evU, s2);

    // main: r-half ru passes (needs CSR)
    cudaStreamWaitEvent(0, evJoin, 0);
    k_spmm<128, 0, 2, 1, 1, 0><<<M_/16, 256>>>(nullptr, nullptr, nullptr);
    k_spmm<128, 0, 1, 0, 0, 1><<<M_/16, 256>>>(hx, b_ru, nullptr);

    // GEMM2 (HMMA): Qc[0..2] += g @ W2   (needs g from r-gate only)
    k_mma_gemm<2><<<dim3(MTILE, NC2/64), 128, DSM>>>();

    // c sparse: Qc1 += A*Qc2 ; then final (needs g_U -> wait evU)
    k_spmm<64, 0, 5, 4, 4, 0><<<M_/16, 256>>>(nullptr, nullptr, nullptr);
    cudaStreamWaitEvent(0, evU, 0);
    k_spmm<64, 0, 4, 3, 0, 2><<<M_/16, 256>>>(hx, b_c, out);
}